// round 8
// baseline (speedup 1.0000x reference)
#include <cuda_runtime.h>
#include <cuda_fp16.h>
#include <cstdint>

#define N_NODES 50000
#define E_EDGES 800000
#define HID 128
#define L_LAYERS 4
#define N_CLASSES 10
#define BN_EPS 1e-5f
#define SCAN_BLOCKS 196   // 196 * 256 = 50176 >= N_NODES

// ---------------- scratch (device globals: no allocation allowed) ----------------
__device__ __align__(256) float  g_bufA[N_NODES * HID];
__device__ __align__(256) float  g_bufB[N_NODES * HID];
__device__ __align__(256) __half g_xh[N_NODES * HID];   // GEMM output for gather
__device__ __align__(256) __half g_hh[N_NODES * HID];   // fp16 copy of h (GEMM A input)
__device__ __align__(256) float  g_agg[N_NODES * HID];
__device__ __align__(256) int    g_cnt[N_NODES];
__device__ __align__(256) int    g_rowptr[N_NODES + 1];
__device__ __align__(256) int    g_col[E_EDGES];
__device__ __align__(256) float  g_dinv[N_NODES];
__device__ __align__(256) int    g_blksum[SCAN_BLOCKS];
__device__ __align__(256) int    g_blkoff[SCAN_BLOCKS];
__device__ __align__(256) float  g_sum[L_LAYERS * HID];
__device__ __align__(256) float  g_sumsq[L_LAYERS * HID];
__device__ int g_is64;

// buffer selector resolved on device (1=g_bufA, 2=g_bufB, 4=g_agg)
__device__ __forceinline__ float* pick(int s) {
    return s == 1 ? g_bufA : s == 2 ? g_bufB : g_agg;
}

// ---------------- edge-index dtype detection ----------------
__global__ void k_detect(const int* __restrict__ w) {
    __shared__ int nz;
    if (threadIdx.x == 0) nz = 0;
    __syncthreads();
    int acc = 0;
    for (int j = threadIdx.x; j < 4096; j += 256) acc |= w[2 * j + 1];
    if (acc) atomicOr(&nz, 1);
    __syncthreads();
    if (threadIdx.x == 0) g_is64 = (nz == 0) ? 1 : 0;
}

// ---------------- setup kernels ----------------
__global__ void k_init() {
    int i = blockIdx.x * blockDim.x + threadIdx.x;
    if (i < N_NODES) g_cnt[i] = 0;
    if (i < L_LAYERS * HID) { g_sum[i] = 0.f; g_sumsq[i] = 0.f; }
}

__global__ void k_count(const int* __restrict__ ei) {
    int j = blockIdx.x * blockDim.x + threadIdx.x;
    if (j >= E_EDGES) return;
    int m = g_is64;
    int dst = ei[(long long)(E_EDGES + j) << m];
    if ((unsigned)dst < N_NODES) atomicAdd(&g_cnt[dst], 1);
}

// ---- 3-kernel parallel exclusive scan over g_cnt ----
__global__ void k_blksum() {
    __shared__ int sh[256];
    int t = threadIdx.x;
    int i = blockIdx.x * 256 + t;
    int c = 0;
    if (i < N_NODES) {
        c = g_cnt[i];
        g_dinv[i] = rsqrtf((float)(c + 1));  // +1 self-loop
    }
    sh[t] = c;
    __syncthreads();
#pragma unroll
    for (int off = 128; off; off >>= 1) {
        if (t < off) sh[t] += sh[t + off];
        __syncthreads();
    }
    if (t == 0) g_blksum[blockIdx.x] = sh[0];
}

__global__ void k_scanblk() {
    __shared__ int sh[256];
    int t = threadIdx.x;
    int v = (t < SCAN_BLOCKS) ? g_blksum[t] : 0;
    sh[t] = v;
    __syncthreads();
#pragma unroll
    for (int off = 1; off < 256; off <<= 1) {
        int u = (t >= off) ? sh[t - off] : 0;
        __syncthreads();
        sh[t] += u;
        __syncthreads();
    }
    if (t < SCAN_BLOCKS) g_blkoff[t] = sh[t] - v;  // exclusive
    if (t == 255) g_rowptr[N_NODES] = sh[255];
}

__global__ void k_rowptr() {
    __shared__ int sh[256];
    int t = threadIdx.x;
    int i = blockIdx.x * 256 + t;
    int c = (i < N_NODES) ? g_cnt[i] : 0;
    sh[t] = c;
    __syncthreads();
#pragma unroll
    for (int off = 1; off < 256; off <<= 1) {
        int u = (t >= off) ? sh[t - off] : 0;
        __syncthreads();
        sh[t] += u;
        __syncthreads();
    }
    if (i < N_NODES) g_rowptr[i] = g_blkoff[blockIdx.x] + sh[t] - c;  // exclusive
}

// fill: reuse g_cnt as down-counting cursor
__global__ void k_fill(const int* __restrict__ ei) {
    int j = blockIdx.x * blockDim.x + threadIdx.x;
    if (j >= E_EDGES) return;
    int m = g_is64;
    int src = ei[(long long)j << m];
    int dst = ei[(long long)(E_EDGES + j) << m];
    if ((unsigned)dst >= N_NODES || (unsigned)src >= N_NODES) return;
    int slot = atomicSub(&g_cnt[dst], 1) - 1;
    g_col[g_rowptr[dst] + slot] = src;
}

// ---------------- fp16 tensor-core GEMM: C[M,128] = A[M,128] @ B[128,128] ----------
// CTA: 128x128 tile, 256 threads = 8 warps (2 M x 4 N), warp tile 64x32.
// mma.sync.m16n8k16 f16*f16 -> f32 accum, ldmatrix operand fetch.
// a_is_half: A = g_hh (fp16); else A = Aext (fp32, converted on smem store).
// emb_mode: write fp32 g_bufA (+bias) AND fp16 g_hh. else: write fp16 g_xh only.
#define SA 72    // A_s row stride in halves (64 chunk + 8 pad)
#define SB 136   // B_s row stride in halves (128 + 8 pad)
__global__ __launch_bounds__(256, 2) void k_gemm_h(const float* __restrict__ Aext,
                                                   int a_is_half,
                                                   const float* __restrict__ B,
                                                   const float* __restrict__ bias,
                                                   int emb_mode, int M) {
    __shared__ __half A_s[128 * SA];
    __shared__ __half B_s[64 * SB];
    int tid = threadIdx.x;
    int lane = tid & 31;
    int wid = tid >> 5;
    int gid = lane >> 2, tig = lane & 3;
    int warp_m = wid & 1, warp_n = wid >> 1;
    int blockM = blockIdx.x * 128;

    float c[4][4][4];
#pragma unroll
    for (int a = 0; a < 4; a++)
#pragma unroll
        for (int b = 0; b < 4; b++)
#pragma unroll
            for (int d = 0; d < 4; d++) c[a][b][d] = 0.f;

#pragma unroll
    for (int kc = 0; kc < 2; kc++) {
        int k0 = kc * 64;
        // ---- load A chunk: 128 rows x 64 halves ----
        {
            int row = tid >> 1, coff = (tid & 1) * 32;
            int grow = blockM + row;
            uint4* dst = (uint4*)&A_s[row * SA + coff];
            if (grow < M) {
                if (a_is_half) {
                    const uint4* src = (const uint4*)&g_hh[(size_t)grow * 128 + k0 + coff];
#pragma unroll
                    for (int q = 0; q < 4; q++) dst[q] = src[q];
                } else {
                    const float4* src = (const float4*)&Aext[(size_t)grow * 128 + k0 + coff];
#pragma unroll
                    for (int q = 0; q < 4; q++) {
                        float4 f0 = src[2 * q], f1 = src[2 * q + 1];
                        __half2 h[4] = {__floats2half2_rn(f0.x, f0.y),
                                        __floats2half2_rn(f0.z, f0.w),
                                        __floats2half2_rn(f1.x, f1.y),
                                        __floats2half2_rn(f1.z, f1.w)};
                        dst[q] = *(uint4*)h;
                    }
                }
            } else {
                uint4 z = make_uint4(0, 0, 0, 0);
#pragma unroll
                for (int q = 0; q < 4; q++) dst[q] = z;
            }
        }
        // ---- load B chunk: 64 k-rows x 128 n (fp32 -> fp16) ----
        {
            int krow = tid >> 2, q4 = tid & 3;
            const float4* src = (const float4*)&B[(size_t)(k0 + krow) * 128 + q4 * 32];
            uint4* dst = (uint4*)&B_s[krow * SB + q4 * 32];
#pragma unroll
            for (int q = 0; q < 4; q++) {
                float4 f0 = src[2 * q], f1 = src[2 * q + 1];
                __half2 h[4] = {__floats2half2_rn(f0.x, f0.y), __floats2half2_rn(f0.z, f0.w),
                                __floats2half2_rn(f1.x, f1.y), __floats2half2_rn(f1.z, f1.w)};
                dst[q] = *(uint4*)h;
            }
        }
        __syncthreads();

#pragma unroll
        for (int kk = 0; kk < 4; kk++) {
            int kb = kk * 16;
            // B fragments: 2x ldmatrix.x4.trans -> 4 n8-tiles
            uint32_t bf[4][2];
            {
                int krow = kb + ((lane & 8) ? 8 : 0) + (lane & 7);
                int ncol = warp_n * 32 + ((lane >> 4) << 3);
#pragma unroll
                for (int pr = 0; pr < 2; pr++) {
                    unsigned addr = (unsigned)__cvta_generic_to_shared(
                        &B_s[krow * SB + ncol + pr * 16]);
                    uint32_t r0, r1, r2, r3;
                    asm volatile(
                        "ldmatrix.sync.aligned.m8n8.x4.trans.shared.b16 {%0,%1,%2,%3}, [%4];"
                        : "=r"(r0), "=r"(r1), "=r"(r2), "=r"(r3) : "r"(addr));
                    bf[pr * 2][0] = r0; bf[pr * 2][1] = r1;
                    bf[pr * 2 + 1][0] = r2; bf[pr * 2 + 1][1] = r3;
                }
            }
#pragma unroll
            for (int mt = 0; mt < 4; mt++) {
                int mrow = warp_m * 64 + mt * 16 + (lane & 15);
                int kcol = kb + ((lane >> 4) << 3);
                unsigned addr = (unsigned)__cvta_generic_to_shared(&A_s[mrow * SA + kcol]);
                uint32_t a0, a1, a2, a3;
                asm volatile("ldmatrix.sync.aligned.m8n8.x4.shared.b16 {%0,%1,%2,%3}, [%4];"
                             : "=r"(a0), "=r"(a1), "=r"(a2), "=r"(a3) : "r"(addr));
#pragma unroll
                for (int nt = 0; nt < 4; nt++) {
                    asm volatile(
                        "mma.sync.aligned.m16n8k16.row.col.f32.f16.f16.f32 "
                        "{%0,%1,%2,%3}, {%4,%5,%6,%7}, {%8,%9}, {%0,%1,%2,%3};"
                        : "+f"(c[mt][nt][0]), "+f"(c[mt][nt][1]), "+f"(c[mt][nt][2]),
                          "+f"(c[mt][nt][3])
                        : "r"(a0), "r"(a1), "r"(a2), "r"(a3), "r"(bf[nt][0]),
                          "r"(bf[nt][1]));
                }
            }
        }
        __syncthreads();
    }

    // ---- epilogue ----
#pragma unroll
    for (int mt = 0; mt < 4; mt++) {
#pragma unroll
        for (int nt = 0; nt < 4; nt++) {
            int col = warp_n * 32 + nt * 8 + tig * 2;
            int r0 = blockM + warp_m * 64 + mt * 16 + gid;
            int r1 = r0 + 8;
            float2 v0 = make_float2(c[mt][nt][0], c[mt][nt][1]);
            float2 v1 = make_float2(c[mt][nt][2], c[mt][nt][3]);
            if (emb_mode) {
                float bx = bias[col], by = bias[col + 1];
                v0.x += bx; v0.y += by; v1.x += bx; v1.y += by;
                if (r0 < M) {
                    *(float2*)&g_bufA[(size_t)r0 * 128 + col] = v0;
                    ((__half2*)g_hh)[((size_t)r0 * 128 + col) >> 1] =
                        __floats2half2_rn(v0.x, v0.y);
                }
                if (r1 < M) {
                    *(float2*)&g_bufA[(size_t)r1 * 128 + col] = v1;
                    ((__half2*)g_hh)[((size_t)r1 * 128 + col) >> 1] =
                        __floats2half2_rn(v1.x, v1.y);
                }
            } else {
                if (r0 < M)
                    ((__half2*)g_xh)[((size_t)r0 * 128 + col) >> 1] =
                        __floats2half2_rn(v0.x, v0.y);
                if (r1 < M)
                    ((__half2*)g_xh)[((size_t)r1 * 128 + col) >> 1] =
                        __floats2half2_rn(v1.x, v1.y);
            }
        }
    }
}

// ---------------- CSR aggregation (fp16 gather) + fused BN stats ----------------
__device__ __forceinline__ float4 ldx_h(int u, int lane) {
    uint2 raw = ((const uint2*)(g_xh + (size_t)u * 128))[lane];
    __half2 h0 = *(__half2*)&raw.x;
    __half2 h1 = *(__half2*)&raw.y;
    float2 f0 = __half22float2(h0);
    float2 f1 = __half22float2(h1);
    return make_float4(f0.x, f0.y, f1.x, f1.y);
}

__global__ void k_agg(const float* __restrict__ bias, int layer) {
    __shared__ float s_sum[8][HID];
    __shared__ float s_ss[8][HID];
    int lane = threadIdx.x & 31;
    int wblk = threadIdx.x >> 5;
    int w = (blockIdx.x * blockDim.x + threadIdx.x) >> 5;
    int nw = (gridDim.x * blockDim.x) >> 5;
    float4 bb = ((const float4*)bias)[lane];
    float4 ls = make_float4(0.f, 0.f, 0.f, 0.f);
    float4 lss = make_float4(0.f, 0.f, 0.f, 0.f);

    for (int v = w; v < N_NODES; v += nw) {
        float dv = g_dinv[v];
        float4 xv = ldx_h(v, lane);
        float4 acc = make_float4(xv.x * dv, xv.y * dv, xv.z * dv, xv.w * dv);  // self-loop
        int s = g_rowptr[v], e = g_rowptr[v + 1];
        int p = s;
        for (; p + 2 <= e; p += 2) {
            int u0 = g_col[p], u1 = g_col[p + 1];
            float d0 = g_dinv[u0], d1 = g_dinv[u1];
            float4 x0 = ldx_h(u0, lane);
            float4 x1 = ldx_h(u1, lane);
            acc.x += x0.x * d0 + x1.x * d1;
            acc.y += x0.y * d0 + x1.y * d1;
            acc.z += x0.z * d0 + x1.z * d1;
            acc.w += x0.w * d0 + x1.w * d1;
        }
        if (p < e) {
            int u = g_col[p];
            float du = g_dinv[u];
            float4 xu = ldx_h(u, lane);
            acc.x += xu.x * du;
            acc.y += xu.y * du;
            acc.z += xu.z * du;
            acc.w += xu.w * du;
        }
        float4 o;
        o.x = acc.x * dv + bb.x;
        o.y = acc.y * dv + bb.y;
        o.z = acc.z * dv + bb.z;
        o.w = acc.w * dv + bb.w;
        ((float4*)(g_agg + (size_t)v * 128))[lane] = o;
        ls.x += o.x; ls.y += o.y; ls.z += o.z; ls.w += o.w;
        lss.x += o.x * o.x; lss.y += o.y * o.y; lss.z += o.z * o.z; lss.w += o.w * o.w;
    }

    ((float4*)&s_sum[wblk][lane * 4])[0] = ls;
    ((float4*)&s_ss[wblk][lane * 4])[0] = lss;
    __syncthreads();
    if (threadIdx.x < HID) {
        int f = threadIdx.x;
        float ts = 0.f, tss = 0.f;
#pragma unroll
        for (int k = 0; k < 8; k++) { ts += s_sum[k][f]; tss += s_ss[k][f]; }
        atomicAdd(&g_sum[layer * HID + f], ts);
        atomicAdd(&g_sumsq[layer * HID + f], tss);
    }
}

// ---------------- apply: hout = hin + relu(agg*scale + shift); also fp16 copy ----
__global__ void k_apply(int hin_sel, int hout_sel, int layer,
                        const float* __restrict__ gamma, const float* __restrict__ beta) {
    __shared__ float s_scale[HID];
    __shared__ float s_shift[HID];
    if (threadIdx.x < HID) {
        int f = threadIdx.x;
        const float invn = 1.0f / (float)N_NODES;
        float mu = g_sum[layer * HID + f] * invn;
        float var = fmaxf(g_sumsq[layer * HID + f] * invn - mu * mu, 0.f);
        float sc = gamma[f] * rsqrtf(var + BN_EPS);
        s_scale[f] = sc;
        s_shift[f] = beta[f] - mu * sc;
    }
    __syncthreads();
    int i = blockIdx.x * blockDim.x + threadIdx.x;  // float4 index
    if (i >= N_NODES * 32) return;
    const float* hin = pick(hin_sel);
    float* hout = pick(hout_sel);
    int f4 = i & 31;
    float4 sc = ((const float4*)s_scale)[f4];
    float4 sh = ((const float4*)s_shift)[f4];
    float4 a = ((const float4*)g_agg)[i];
    float4 h = ((const float4*)hin)[i];
    float4 o;
    o.x = h.x + fmaxf(a.x * sc.x + sh.x, 0.f);
    o.y = h.y + fmaxf(a.y * sc.y + sh.y, 0.f);
    o.z = h.z + fmaxf(a.z * sc.z + sh.z, 0.f);
    o.w = h.w + fmaxf(a.w * sc.w + sh.w, 0.f);
    ((float4*)hout)[i] = o;
    __half2 hh[2] = {__floats2half2_rn(o.x, o.y), __floats2half2_rn(o.z, o.w)};
    ((uint2*)g_hh)[i] = *(uint2*)hh;
}

// ---------------- final classifier: warp per row, W in registers ----------------
__global__ void k_final(int h_sel, const float* __restrict__ W,
                        const float* __restrict__ b, float* __restrict__ out) {
    int lane = threadIdx.x & 31;
    int w0 = (blockIdx.x * blockDim.x + threadIdx.x) >> 5;
    int nw = (gridDim.x * blockDim.x) >> 5;
    const float* h = pick(h_sel);
    float wr[4][N_CLASSES];
#pragma unroll
    for (int j = 0; j < 4; j++)
#pragma unroll
        for (int c = 0; c < N_CLASSES; c++) wr[j][c] = W[(lane * 4 + j) * N_CLASSES + c];
    for (int row = w0; row < N_NODES; row += nw) {
        float4 hv = ((const float4*)(h + (size_t)row * 128))[lane];
        float p[N_CLASSES];
#pragma unroll
        for (int c = 0; c < N_CLASSES; c++)
            p[c] = hv.x * wr[0][c] + hv.y * wr[1][c] + hv.z * wr[2][c] + hv.w * wr[3][c];
#pragma unroll
        for (int c = 0; c < N_CLASSES; c++)
#pragma unroll
            for (int off = 16; off; off >>= 1)
                p[c] += __shfl_xor_sync(0xffffffffu, p[c], off);
        if (lane == 0) {
#pragma unroll
            for (int c = 0; c < N_CLASSES; c++) out[(size_t)row * N_CLASSES + c] = p[c] + b[c];
        }
    }
}

// ---------------- launch ----------------
extern "C" void kernel_launch(void* const* d_in, const int* in_sizes, int n_in,
                              void* d_out, int out_size) {
    const float* h_in = (const float*)d_in[0];
    const int* ei = (const int*)d_in[1];   // int32 or int64 (auto-detected)
    const float* W_emb = (const float*)d_in[3];
    const float* b_emb = (const float*)d_in[4];
    const float* Ws = (const float*)d_in[5];
    const float* bs = (const float*)d_in[6];
    const float* gammas = (const float*)d_in[7];
    const float* betas = (const float*)d_in[8];
    const float* W_mlp = (const float*)d_in[9];
    const float* b_mlp = (const float*)d_in[10];
    float* out = (float*)d_out;

    k_detect<<<1, 256>>>(ei);
    k_init<<<196, 256>>>();
    k_count<<<E_EDGES / 256, 256>>>(ei);
    k_blksum<<<SCAN_BLOCKS, 256>>>();
    k_scanblk<<<1, 256>>>();
    k_rowptr<<<SCAN_BLOCKS, 256>>>();
    k_fill<<<E_EDGES / 256, 256>>>(ei);

    const int gemm_grid = (N_NODES + 127) / 128;  // 391
    // embedding: bufA(fp32) + g_hh(fp16) = h_in @ W_emb + b_emb
    k_gemm_h<<<gemm_grid, 256>>>(h_in, 0, W_emb, b_emb, 1, N_NODES);

    int hc = 1, ho = 2;  // selectors: 1=bufA, 2=bufB
    for (int i = 0; i < L_LAYERS; i++) {
        k_gemm_h<<<gemm_grid, 256>>>(nullptr, 1, Ws + (size_t)i * HID * HID, nullptr, 0,
                                     N_NODES);
        k_agg<<<1024, 256>>>(bs + i * HID, i);
        k_apply<<<(N_NODES * 32 + 255) / 256, 256>>>(hc, ho, i, gammas + i * HID,
                                                     betas + i * HID);
        int t = hc; hc = ho; ho = t;
    }
    k_final<<<6250, 256>>>(hc, W_mlp, b_mlp, out);
}

// round 10
// speedup vs baseline: 1.1826x; 1.1826x over previous
#include <cuda_runtime.h>
#include <cuda_fp16.h>
#include <cstdint>

#define N_NODES 50000
#define E_EDGES 800000
#define HID 128
#define L_LAYERS 4
#define N_CLASSES 10
#define BN_EPS 1e-5f
#define SCAN_BLOCKS 196   // 196 * 256 = 50176 >= N_NODES

// ---------------- scratch (device globals: no allocation allowed) ----------------
__device__ __align__(256) float  g_bufA[N_NODES * HID];
__device__ __align__(256) float  g_bufB[N_NODES * HID];
__device__ __align__(256) __half g_xh[N_NODES * HID];   // GEMM output for gather
__device__ __align__(256) float  g_agg[N_NODES * HID];
__device__ __align__(256) int    g_cnt[N_NODES];
__device__ __align__(256) int    g_rowptr[N_NODES + 1];
__device__ __align__(256) int    g_col[E_EDGES];
__device__ __align__(256) float  g_dinv[N_NODES];
__device__ __align__(256) int    g_blksum[SCAN_BLOCKS];
__device__ __align__(256) int    g_blkoff[SCAN_BLOCKS];
__device__ __align__(256) float  g_sum[L_LAYERS * HID];
__device__ __align__(256) float  g_sumsq[L_LAYERS * HID];
__device__ int g_is64;

// buffer selector resolved on device (1=g_bufA, 2=g_bufB, else g_agg)
__device__ __forceinline__ float* pick(int s) {
    return s == 1 ? g_bufA : s == 2 ? g_bufB : g_agg;
}

// ---------------- f32x2 packed-FMA helpers (Blackwell FFMA2) ----------------
__device__ __forceinline__ unsigned long long dup2(float x) {
    unsigned long long r;
    asm("mov.b64 %0, {%1, %1};" : "=l"(r) : "f"(x));
    return r;
}
__device__ __forceinline__ void fma2(unsigned long long& d, unsigned long long a,
                                     unsigned long long b) {
    asm("fma.rn.f32x2 %0, %1, %2, %0;" : "+l"(d) : "l"(a), "l"(b));
}
__device__ __forceinline__ float2 unpk2(unsigned long long v) {
    float2 f;
    asm("mov.b64 {%0, %1}, %2;" : "=f"(f.x), "=f"(f.y) : "l"(v));
    return f;
}

// ---------------- edge-index dtype detection ----------------
__global__ void k_detect(const int* __restrict__ w) {
    __shared__ int nz;
    if (threadIdx.x == 0) nz = 0;
    __syncthreads();
    int acc = 0;
    for (int j = threadIdx.x; j < 4096; j += 256) acc |= w[2 * j + 1];
    if (acc) atomicOr(&nz, 1);
    __syncthreads();
    if (threadIdx.x == 0) g_is64 = (nz == 0) ? 1 : 0;
}

// ---------------- setup kernels ----------------
__global__ void k_init() {
    int i = blockIdx.x * blockDim.x + threadIdx.x;
    if (i < N_NODES) g_cnt[i] = 0;
    if (i < L_LAYERS * HID) { g_sum[i] = 0.f; g_sumsq[i] = 0.f; }
}

__global__ void k_count(const int* __restrict__ ei) {
    int j = blockIdx.x * blockDim.x + threadIdx.x;
    if (j >= E_EDGES) return;
    int m = g_is64;
    int dst = ei[(long long)(E_EDGES + j) << m];
    if ((unsigned)dst < N_NODES) atomicAdd(&g_cnt[dst], 1);
}

__global__ void k_blksum() {
    __shared__ int sh[256];
    int t = threadIdx.x;
    int i = blockIdx.x * 256 + t;
    int c = 0;
    if (i < N_NODES) {
        c = g_cnt[i];
        g_dinv[i] = rsqrtf((float)(c + 1));  // +1 self-loop
    }
    sh[t] = c;
    __syncthreads();
#pragma unroll
    for (int off = 128; off; off >>= 1) {
        if (t < off) sh[t] += sh[t + off];
        __syncthreads();
    }
    if (t == 0) g_blksum[blockIdx.x] = sh[0];
}

__global__ void k_scanblk() {
    __shared__ int sh[256];
    int t = threadIdx.x;
    int v = (t < SCAN_BLOCKS) ? g_blksum[t] : 0;
    sh[t] = v;
    __syncthreads();
#pragma unroll
    for (int off = 1; off < 256; off <<= 1) {
        int u = (t >= off) ? sh[t - off] : 0;
        __syncthreads();
        sh[t] += u;
        __syncthreads();
    }
    if (t < SCAN_BLOCKS) g_blkoff[t] = sh[t] - v;
    if (t == 255) g_rowptr[N_NODES] = sh[255];
}

__global__ void k_rowptr() {
    __shared__ int sh[256];
    int t = threadIdx.x;
    int i = blockIdx.x * 256 + t;
    int c = (i < N_NODES) ? g_cnt[i] : 0;
    sh[t] = c;
    __syncthreads();
#pragma unroll
    for (int off = 1; off < 256; off <<= 1) {
        int u = (t >= off) ? sh[t - off] : 0;
        __syncthreads();
        sh[t] += u;
        __syncthreads();
    }
    if (i < N_NODES) g_rowptr[i] = g_blkoff[blockIdx.x] + sh[t] - c;
}

__global__ void k_fill(const int* __restrict__ ei) {
    int j = blockIdx.x * blockDim.x + threadIdx.x;
    if (j >= E_EDGES) return;
    int m = g_is64;
    int src = ei[(long long)j << m];
    int dst = ei[(long long)(E_EDGES + j) << m];
    if ((unsigned)dst >= N_NODES || (unsigned)src >= N_NODES) return;
    int slot = atomicSub(&g_cnt[dst], 1) - 1;
    g_col[g_rowptr[dst] + slot] = src;
}

// ---------------- SGEMM (FFMA2) with optional fused BN-apply A-phase ----------------
// C[M,128] = A[M,128] @ B[128,128].
// fuse=0: A = Aext (asel=0) or pick(asel).
// fuse=1: A_row = hin + relu(agg*scale + shift)  (BN of `layer`), also written to hout.
// half_out=1: write g_xh fp16. else write pick(csel) fp32 (+bias).
#define BK 16
#define AST 136
__global__ __launch_bounds__(256, 2) void k_gemm(
    const float* __restrict__ Aext, int asel, const float* __restrict__ B,
    const float* __restrict__ bias, int csel, int half_out, int fuse, int hin_sel,
    int hout_sel, int layer, const float* __restrict__ gamma,
    const float* __restrict__ beta, int M) {
    __shared__ float As[BK][AST];   // [k][m]
    __shared__ float Bs[BK][128];   // [k][n]
    __shared__ float s_scale[HID];
    __shared__ float s_shift[HID];

    const float* A;
    const float* Hin = nullptr;
    float* Hout = nullptr;
    if (fuse) {
        A = g_agg;
        Hin = pick(hin_sel);
        Hout = pick(hout_sel);
        if (threadIdx.x < HID) {
            int f = threadIdx.x;
            const float invn = 1.0f / (float)N_NODES;
            float mu = g_sum[layer * HID + f] * invn;
            float var = fmaxf(g_sumsq[layer * HID + f] * invn - mu * mu, 0.f);
            float sc = gamma[f] * rsqrtf(var + BN_EPS);
            s_scale[f] = sc;
            s_shift[f] = beta[f] - mu * sc;
        }
        __syncthreads();
    } else {
        A = (asel == 0) ? Aext : pick(asel);
    }
    float* C = pick(csel);
    int tid = threadIdx.x;
    int tx = tid & 15;   // n dim
    int ty = tid >> 4;   // m dim
    int blockM = blockIdx.x * 128;

    int a_m0 = tid >> 2, a_kq0 = tid & 3;
    int a_m1 = (tid + 256) >> 2, a_kq1 = a_kq0;
    int b_k0 = tid >> 5, b_n40 = tid & 31;
    int b_k1 = (tid + 256) >> 5, b_n41 = b_n40;
    int r0 = blockM + a_m0, r1 = blockM + a_m1;
    bool ok0 = r0 < M, ok1 = r1 < M;
    const float4 z4 = make_float4(0.f, 0.f, 0.f, 0.f);

    unsigned long long acc[8][4];
#pragma unroll
    for (int i = 0; i < 8; i++)
#pragma unroll
        for (int j = 0; j < 4; j++) acc[i][j] = 0ull;

    float4 pa0, pa1, pb0, pb1, qa0, qa1;
    {
        pa0 = ok0 ? *(const float4*)&A[(size_t)r0 * 128 + a_kq0 * 4] : z4;
        pa1 = ok1 ? *(const float4*)&A[(size_t)r1 * 128 + a_kq1 * 4] : z4;
        if (fuse) {
            qa0 = ok0 ? *(const float4*)&Hin[(size_t)r0 * 128 + a_kq0 * 4] : z4;
            qa1 = ok1 ? *(const float4*)&Hin[(size_t)r1 * 128 + a_kq1 * 4] : z4;
        }
        pb0 = *(const float4*)&B[(size_t)b_k0 * 128 + b_n40 * 4];
        pb1 = *(const float4*)&B[(size_t)b_k1 * 128 + b_n41 * 4];
    }

#pragma unroll
    for (int kc = 0; kc < 8; kc++) {
        int k0 = kc * BK;
        float4 o0 = pa0, o1 = pa1;
        if (fuse) {
            float4 sc = *(const float4*)&s_scale[k0 + a_kq0 * 4];
            float4 sh = *(const float4*)&s_shift[k0 + a_kq0 * 4];
            o0.x = qa0.x + fmaxf(pa0.x * sc.x + sh.x, 0.f);
            o0.y = qa0.y + fmaxf(pa0.y * sc.y + sh.y, 0.f);
            o0.z = qa0.z + fmaxf(pa0.z * sc.z + sh.z, 0.f);
            o0.w = qa0.w + fmaxf(pa0.w * sc.w + sh.w, 0.f);
            o1.x = qa1.x + fmaxf(pa1.x * sc.x + sh.x, 0.f);
            o1.y = qa1.y + fmaxf(pa1.y * sc.y + sh.y, 0.f);
            o1.z = qa1.z + fmaxf(pa1.z * sc.z + sh.z, 0.f);
            o1.w = qa1.w + fmaxf(pa1.w * sc.w + sh.w, 0.f);
            if (ok0) *(float4*)&Hout[(size_t)r0 * 128 + k0 + a_kq0 * 4] = o0;
            if (ok1) *(float4*)&Hout[(size_t)r1 * 128 + k0 + a_kq1 * 4] = o1;
        }
        As[a_kq0 * 4 + 0][a_m0] = o0.x;
        As[a_kq0 * 4 + 1][a_m0] = o0.y;
        As[a_kq0 * 4 + 2][a_m0] = o0.z;
        As[a_kq0 * 4 + 3][a_m0] = o0.w;
        As[a_kq1 * 4 + 0][a_m1] = o1.x;
        As[a_kq1 * 4 + 1][a_m1] = o1.y;
        As[a_kq1 * 4 + 2][a_m1] = o1.z;
        As[a_kq1 * 4 + 3][a_m1] = o1.w;
        *(float4*)&Bs[b_k0][b_n40 * 4] = pb0;
        *(float4*)&Bs[b_k1][b_n41 * 4] = pb1;
        __syncthreads();

        if (kc < 7) {
            int kn = k0 + BK;
            pa0 = ok0 ? *(const float4*)&A[(size_t)r0 * 128 + kn + a_kq0 * 4] : z4;
            pa1 = ok1 ? *(const float4*)&A[(size_t)r1 * 128 + kn + a_kq1 * 4] : z4;
            if (fuse) {
                qa0 = ok0 ? *(const float4*)&Hin[(size_t)r0 * 128 + kn + a_kq0 * 4] : z4;
                qa1 = ok1 ? *(const float4*)&Hin[(size_t)r1 * 128 + kn + a_kq1 * 4] : z4;
            }
            pb0 = *(const float4*)&B[(size_t)(kn + b_k0) * 128 + b_n40 * 4];
            pb1 = *(const float4*)&B[(size_t)(kn + b_k1) * 128 + b_n41 * 4];
        }

#pragma unroll
        for (int kk = 0; kk < BK; kk++) {
            float4 a0 = *(const float4*)&As[kk][ty * 8];
            float4 a1 = *(const float4*)&As[kk][ty * 8 + 4];
            const unsigned long long* bp = (const unsigned long long*)&Bs[kk][tx * 8];
            unsigned long long b0 = bp[0], b1 = bp[1], b2 = bp[2], b3 = bp[3];
            float av[8] = {a0.x, a0.y, a0.z, a0.w, a1.x, a1.y, a1.z, a1.w};
#pragma unroll
            for (int i = 0; i < 8; i++) {
                unsigned long long ai = dup2(av[i]);
                fma2(acc[i][0], ai, b0);
                fma2(acc[i][1], ai, b1);
                fma2(acc[i][2], ai, b2);
                fma2(acc[i][3], ai, b3);
            }
        }
        __syncthreads();
    }

    float bv[8] = {0.f, 0.f, 0.f, 0.f, 0.f, 0.f, 0.f, 0.f};
    if (bias) {
#pragma unroll
        for (int j = 0; j < 8; j++) bv[j] = bias[tx * 8 + j];
    }
#pragma unroll
    for (int i = 0; i < 8; i++) {
        int row = blockM + ty * 8 + i;
        if (row >= M) continue;
        float2 p0 = unpk2(acc[i][0]), p1 = unpk2(acc[i][1]);
        float2 p2 = unpk2(acc[i][2]), p3 = unpk2(acc[i][3]);
        float c[8] = {p0.x + bv[0], p0.y + bv[1], p1.x + bv[2], p1.y + bv[3],
                      p2.x + bv[4], p2.y + bv[5], p3.x + bv[6], p3.y + bv[7]};
        if (half_out) {
            __half2 h[4];
#pragma unroll
            for (int j = 0; j < 4; j++) h[j] = __floats2half2_rn(c[2 * j], c[2 * j + 1]);
            *(uint4*)&g_xh[(size_t)row * 128 + tx * 8] = *(uint4*)h;
        } else {
            *(float4*)&C[(size_t)row * 128 + tx * 8] = make_float4(c[0], c[1], c[2], c[3]);
            *(float4*)&C[(size_t)row * 128 + tx * 8 + 4] =
                make_float4(c[4], c[5], c[6], c[7]);
        }
    }
}

// ---------------- CSR aggregation (fp16 gather) + fused BN stats ----------------
__device__ __forceinline__ float4 ldx_h(int u, int lane) {
    uint2 raw = ((const uint2*)(g_xh + (size_t)u * 128))[lane];
    __half2 h0 = *(__half2*)&raw.x;
    __half2 h1 = *(__half2*)&raw.y;
    float2 f0 = __half22float2(h0);
    float2 f1 = __half22float2(h1);
    return make_float4(f0.x, f0.y, f1.x, f1.y);
}

__global__ void k_agg(const float* __restrict__ bias, int layer) {
    __shared__ float s_sum[8][HID];
    __shared__ float s_ss[8][HID];
    int lane = threadIdx.x & 31;
    int wblk = threadIdx.x >> 5;
    int w = (blockIdx.x * blockDim.x + threadIdx.x) >> 5;
    int nw = (gridDim.x * blockDim.x) >> 5;
    float4 bb = ((const float4*)bias)[lane];
    float4 ls = make_float4(0.f, 0.f, 0.f, 0.f);
    float4 lss = make_float4(0.f, 0.f, 0.f, 0.f);

    for (int v = w; v < N_NODES; v += nw) {
        float dv = g_dinv[v];
        float4 xv = ldx_h(v, lane);
        float4 acc = make_float4(xv.x * dv, xv.y * dv, xv.z * dv, xv.w * dv);
        int s = g_rowptr[v], e = g_rowptr[v + 1];
        int p = s;
        for (; p + 4 <= e; p += 4) {
            int u0 = g_col[p], u1 = g_col[p + 1], u2 = g_col[p + 2], u3 = g_col[p + 3];
            float d0 = g_dinv[u0], d1 = g_dinv[u1], d2 = g_dinv[u2], d3 = g_dinv[u3];
            float4 x0 = ldx_h(u0, lane);
            float4 x1 = ldx_h(u1, lane);
            float4 x2 = ldx_h(u2, lane);
            float4 x3 = ldx_h(u3, lane);
            acc.x += x0.x * d0 + x1.x * d1 + x2.x * d2 + x3.x * d3;
            acc.y += x0.y * d0 + x1.y * d1 + x2.y * d2 + x3.y * d3;
            acc.z += x0.z * d0 + x1.z * d1 + x2.z * d2 + x3.z * d3;
            acc.w += x0.w * d0 + x1.w * d1 + x2.w * d2 + x3.w * d3;
        }
        for (; p < e; p++) {
            int u = g_col[p];
            float du = g_dinv[u];
            float4 xu = ldx_h(u, lane);
            acc.x += xu.x * du;
            acc.y += xu.y * du;
            acc.z += xu.z * du;
            acc.w += xu.w * du;
        }
        float4 o;
        o.x = acc.x * dv + bb.x;
        o.y = acc.y * dv + bb.y;
        o.z = acc.z * dv + bb.z;
        o.w = acc.w * dv + bb.w;
        ((float4*)(g_agg + (size_t)v * 128))[lane] = o;
        ls.x += o.x; ls.y += o.y; ls.z += o.z; ls.w += o.w;
        lss.x += o.x * o.x; lss.y += o.y * o.y; lss.z += o.z * o.z; lss.w += o.w * o.w;
    }

    ((float4*)&s_sum[wblk][lane * 4])[0] = ls;
    ((float4*)&s_ss[wblk][lane * 4])[0] = lss;
    __syncthreads();
    if (threadIdx.x < HID) {
        int f = threadIdx.x;
        float ts = 0.f, tss = 0.f;
#pragma unroll
        for (int k = 0; k < 8; k++) { ts += s_sum[k][f]; tss += s_ss[k][f]; }
        atomicAdd(&g_sum[layer * HID + f], ts);
        atomicAdd(&g_sumsq[layer * HID + f], tss);
    }
}

// ---------------- apply (last layer only): hout = hin + relu(agg*scale+shift) ------
__global__ void k_apply(int hin_sel, int hout_sel, int layer,
                        const float* __restrict__ gamma, const float* __restrict__ beta) {
    __shared__ float s_scale[HID];
    __shared__ float s_shift[HID];
    if (threadIdx.x < HID) {
        int f = threadIdx.x;
        const float invn = 1.0f / (float)N_NODES;
        float mu = g_sum[layer * HID + f] * invn;
        float var = fmaxf(g_sumsq[layer * HID + f] * invn - mu * mu, 0.f);
        float sc = gamma[f] * rsqrtf(var + BN_EPS);
        s_scale[f] = sc;
        s_shift[f] = beta[f] - mu * sc;
    }
    __syncthreads();
    int i = blockIdx.x * blockDim.x + threadIdx.x;
    if (i >= N_NODES * 32) return;
    const float* hin = pick(hin_sel);
    float* hout = pick(hout_sel);
    int f4 = i & 31;
    float4 sc = ((const float4*)s_scale)[f4];
    float4 sh = ((const float4*)s_shift)[f4];
    float4 a = ((const float4*)g_agg)[i];
    float4 h = ((const float4*)hin)[i];
    float4 o;
    o.x = h.x + fmaxf(a.x * sc.x + sh.x, 0.f);
    o.y = h.y + fmaxf(a.y * sc.y + sh.y, 0.f);
    o.z = h.z + fmaxf(a.z * sc.z + sh.z, 0.f);
    o.w = h.w + fmaxf(a.w * sc.w + sh.w, 0.f);
    ((float4*)hout)[i] = o;
}

// ---------------- final classifier: warp per row, W in registers ----------------
__global__ void k_final(int h_sel, const float* __restrict__ W,
                        const float* __restrict__ b, float* __restrict__ out) {
    int lane = threadIdx.x & 31;
    int w0 = (blockIdx.x * blockDim.x + threadIdx.x) >> 5;
    int nw = (gridDim.x * blockDim.x) >> 5;
    const float* h = pick(h_sel);
    float wr[4][N_CLASSES];
#pragma unroll
    for (int j = 0; j < 4; j++)
#pragma unroll
        for (int c = 0; c < N_CLASSES; c++) wr[j][c] = W[(lane * 4 + j) * N_CLASSES + c];
    for (int row = w0; row < N_NODES; row += nw) {
        float4 hv = ((const float4*)(h + (size_t)row * 128))[lane];
        float p[N_CLASSES];
#pragma unroll
        for (int c = 0; c < N_CLASSES; c++)
            p[c] = hv.x * wr[0][c] + hv.y * wr[1][c] + hv.z * wr[2][c] + hv.w * wr[3][c];
#pragma unroll
        for (int c = 0; c < N_CLASSES; c++)
#pragma unroll
            for (int off = 16; off; off >>= 1)
                p[c] += __shfl_xor_sync(0xffffffffu, p[c], off);
        if (lane == 0) {
#pragma unroll
            for (int c = 0; c < N_CLASSES; c++) out[(size_t)row * N_CLASSES + c] = p[c] + b[c];
        }
    }
}

// ---------------- launch ----------------
extern "C" void kernel_launch(void* const* d_in, const int* in_sizes, int n_in,
                              void* d_out, int out_size) {
    const float* h_in = (const float*)d_in[0];
    const int* ei = (const int*)d_in[1];   // int32 or int64 (auto-detected)
    const float* W_emb = (const float*)d_in[3];
    const float* b_emb = (const float*)d_in[4];
    const float* Ws = (const float*)d_in[5];
    const float* bs = (const float*)d_in[6];
    const float* gammas = (const float*)d_in[7];
    const float* betas = (const float*)d_in[8];
    const float* W_mlp = (const float*)d_in[9];
    const float* b_mlp = (const float*)d_in[10];
    float* out = (float*)d_out;

    k_detect<<<1, 256>>>(ei);
    k_init<<<196, 256>>>();
    k_count<<<E_EDGES / 256, 256>>>(ei);
    k_blksum<<<SCAN_BLOCKS, 256>>>();
    k_scanblk<<<1, 256>>>();
    k_rowptr<<<SCAN_BLOCKS, 256>>>();
    k_fill<<<E_EDGES / 256, 256>>>(ei);

    const int gemm_grid = (N_NODES + 127) / 128;  // 391

    // embedding: bufA = h_in @ W_emb + b_emb  (fp32 out)
    k_gemm<<<gemm_grid, 256>>>(h_in, 0, W_emb, b_emb, 1, 0, 0, 0, 0, 0, nullptr, nullptr,
                               N_NODES);
    // L0 GEMM: x = bufA @ W0  (fp16 out)
    k_gemm<<<gemm_grid, 256>>>(nullptr, 1, Ws, nullptr, 0, 1, 0, 0, 0, 0, nullptr,
                               nullptr, N_NODES);
    k_agg<<<1024, 256>>>(bs, 0);
    // L1 GEMM fused with L0 apply: h1=bufB, x = h1 @ W1
    k_gemm<<<gemm_grid, 256>>>(nullptr, 0, Ws + 1 * HID * HID, nullptr, 0, 1, 1, 1, 2, 0,
                               gammas, betas, N_NODES);
    k_agg<<<1024, 256>>>(bs + 1 * HID, 1);
    // L2 GEMM fused with L1 apply: h2=bufA
    k_gemm<<<gemm_grid, 256>>>(nullptr, 0, Ws + 2 * HID * HID, nullptr, 0, 1, 1, 2, 1, 1,
                               gammas + 1 * HID, betas + 1 * HID, N_NODES);
    k_agg<<<1024, 256>>>(bs + 2 * HID, 2);
    // L3 GEMM fused with L2 apply: h3=bufB
    k_gemm<<<gemm_grid, 256>>>(nullptr, 0, Ws + 3 * HID * HID, nullptr, 0, 1, 1, 1, 2, 2,
                               gammas + 2 * HID, betas + 2 * HID, N_NODES);
    k_agg<<<1024, 256>>>(bs + 3 * HID, 3);
    // L3 apply: h4 = bufB + relu(BN3(agg)) -> bufA
    k_apply<<<(N_NODES * 32 + 255) / 256, 256>>>(2, 1, 3, gammas + 3 * HID,
                                                 betas + 3 * HID);
    k_final<<<6250, 256>>>(1, W_mlp, b_mlp, out);
}

// round 11
// speedup vs baseline: 1.3280x; 1.1230x over previous
#include <cuda_runtime.h>
#include <cuda_fp16.h>
#include <cstdint>

#define N_NODES 50000
#define E_EDGES 800000
#define HID 128
#define L_LAYERS 4
#define N_CLASSES 10
#define BN_EPS 1e-5f
#define SCAN_BLOCKS 196   // 196 * 256 = 50176 >= N_NODES

// ---------------- scratch (device globals: no allocation allowed) ----------------
__device__ __align__(256) float  g_bufA[N_NODES * HID];
__device__ __align__(256) float  g_bufB[N_NODES * HID];
__device__ __align__(256) __half g_xh[N_NODES * HID];   // GEMM output for gather
__device__ __align__(256) float  g_agg[N_NODES * HID];
__device__ __align__(256) int    g_cnt[N_NODES];
__device__ __align__(256) int    g_rowptr[N_NODES + 1];
__device__ __align__(256) int    g_col[E_EDGES];
__device__ __align__(256) float  g_dinv[N_NODES];
__device__ __align__(256) int    g_blksum[SCAN_BLOCKS];
__device__ __align__(256) int    g_blkoff[SCAN_BLOCKS];
__device__ __align__(256) float  g_sum[L_LAYERS * HID];
__device__ __align__(256) float  g_sumsq[L_LAYERS * HID];
__device__ int g_is64;

// buffer selector resolved on device (1=g_bufA, 2=g_bufB, else g_agg)
__device__ __forceinline__ float* pick(int s) {
    return s == 1 ? g_bufA : s == 2 ? g_bufB : g_agg;
}

// ---------------- f32x2 packed-FMA helpers (Blackwell FFMA2) ----------------
__device__ __forceinline__ unsigned long long dup2(float x) {
    unsigned long long r;
    asm("mov.b64 %0, {%1, %1};" : "=l"(r) : "f"(x));
    return r;
}
__device__ __forceinline__ void fma2(unsigned long long& d, unsigned long long a,
                                     unsigned long long b) {
    asm("fma.rn.f32x2 %0, %1, %2, %0;" : "+l"(d) : "l"(a), "l"(b));
}
__device__ __forceinline__ float2 unpk2(unsigned long long v) {
    float2 f;
    asm("mov.b64 {%0, %1}, %2;" : "=f"(f.x), "=f"(f.y) : "l"(v));
    return f;
}

// ---------------- init + edge-index dtype detection (merged) ----------------
__global__ void k_init(const int* __restrict__ w) {
    int i = blockIdx.x * blockDim.x + threadIdx.x;
    if (i < N_NODES) g_cnt[i] = 0;
    if (i < L_LAYERS * HID) { g_sum[i] = 0.f; g_sumsq[i] = 0.f; }
    if (blockIdx.x == 0) {
        __shared__ int nz;
        if (threadIdx.x == 0) nz = 0;
        __syncthreads();
        int acc = 0;
        for (int j = threadIdx.x; j < 4096; j += 256) acc |= w[2 * j + 1];
        if (acc) atomicOr(&nz, 1);
        __syncthreads();
        if (threadIdx.x == 0) g_is64 = (nz == 0) ? 1 : 0;
    }
}

__global__ void k_count(const int* __restrict__ ei) {
    int j = blockIdx.x * blockDim.x + threadIdx.x;
    if (j >= E_EDGES) return;
    int m = g_is64;
    int dst = ei[(long long)(E_EDGES + j) << m];
    if ((unsigned)dst < N_NODES) atomicAdd(&g_cnt[dst], 1);
}

__global__ void k_blksum() {
    __shared__ int sh[256];
    int t = threadIdx.x;
    int i = blockIdx.x * 256 + t;
    int c = 0;
    if (i < N_NODES) {
        c = g_cnt[i];
        g_dinv[i] = rsqrtf((float)(c + 1));  // +1 self-loop
    }
    sh[t] = c;
    __syncthreads();
#pragma unroll
    for (int off = 128; off; off >>= 1) {
        if (t < off) sh[t] += sh[t + off];
        __syncthreads();
    }
    if (t == 0) g_blksum[blockIdx.x] = sh[0];
}

__global__ void k_scanblk() {
    __shared__ int sh[256];
    int t = threadIdx.x;
    int v = (t < SCAN_BLOCKS) ? g_blksum[t] : 0;
    sh[t] = v;
    __syncthreads();
#pragma unroll
    for (int off = 1; off < 256; off <<= 1) {
        int u = (t >= off) ? sh[t - off] : 0;
        __syncthreads();
        sh[t] += u;
        __syncthreads();
    }
    if (t < SCAN_BLOCKS) g_blkoff[t] = sh[t] - v;
    if (t == 255) g_rowptr[N_NODES] = sh[255];
}

__global__ void k_rowptr() {
    __shared__ int sh[256];
    int t = threadIdx.x;
    int i = blockIdx.x * 256 + t;
    int c = (i < N_NODES) ? g_cnt[i] : 0;
    sh[t] = c;
    __syncthreads();
#pragma unroll
    for (int off = 1; off < 256; off <<= 1) {
        int u = (t >= off) ? sh[t - off] : 0;
        __syncthreads();
        sh[t] += u;
        __syncthreads();
    }
    if (i < N_NODES) g_rowptr[i] = g_blkoff[blockIdx.x] + sh[t] - c;
}

__global__ void k_fill(const int* __restrict__ ei) {
    int j = blockIdx.x * blockDim.x + threadIdx.x;
    if (j >= E_EDGES) return;
    int m = g_is64;
    int src = ei[(long long)j << m];
    int dst = ei[(long long)(E_EDGES + j) << m];
    if ((unsigned)dst >= N_NODES || (unsigned)src >= N_NODES) return;
    int slot = atomicSub(&g_cnt[dst], 1) - 1;
    g_col[g_rowptr[dst] + slot] = src;
}

// ---------------- SGEMM: C[M,128] = A[M,128] @ B[128,128] (+bias) ----------------
// 128x128 tile, 256 threads, 8x8 microtile, packed f32x2 FMAs.
// Double-buffered smem: one __syncthreads per K-chunk; prefetch LDGs issued
// before the FMA block so global latency overlaps compute.
// half_out: write g_xh (fp16) instead of float C.
#define BK 16
#define AST 136
__global__ __launch_bounds__(256, 2) void k_gemm(const float* __restrict__ Aext, int asel,
                                                 const float* __restrict__ B,
                                                 const float* __restrict__ bias, int csel,
                                                 int half_out, int M) {
    __shared__ float As[2][BK][AST];   // [buf][k][m]
    __shared__ float Bs[2][BK][128];   // [buf][k][n]
    const float* A = (asel == 0) ? Aext : pick(asel);
    float* C = pick(csel);
    int tid = threadIdx.x;
    int tx = tid & 15;   // n dim
    int ty = tid >> 4;   // m dim
    int blockM = blockIdx.x * 128;

    int a_m0 = tid >> 2, a_kq0 = tid & 3;
    int a_m1 = (tid + 256) >> 2, a_kq1 = a_kq0;
    int b_k0 = tid >> 5, b_n40 = tid & 31;
    int b_k1 = (tid + 256) >> 5, b_n41 = b_n40;
    int r0 = blockM + a_m0, r1 = blockM + a_m1;
    bool ok0 = r0 < M, ok1 = r1 < M;
    const float4 z4 = make_float4(0.f, 0.f, 0.f, 0.f);

    unsigned long long acc[8][4];
#pragma unroll
    for (int i = 0; i < 8; i++)
#pragma unroll
        for (int j = 0; j < 4; j++) acc[i][j] = 0ull;

    float4 pa0, pa1, pb0, pb1;
    // prefetch chunk 0
    pa0 = ok0 ? *(const float4*)&A[(size_t)r0 * 128 + a_kq0 * 4] : z4;
    pa1 = ok1 ? *(const float4*)&A[(size_t)r1 * 128 + a_kq1 * 4] : z4;
    pb0 = *(const float4*)&B[(size_t)b_k0 * 128 + b_n40 * 4];
    pb1 = *(const float4*)&B[(size_t)b_k1 * 128 + b_n41 * 4];
    // store chunk 0 -> buf 0
    As[0][a_kq0 * 4 + 0][a_m0] = pa0.x;
    As[0][a_kq0 * 4 + 1][a_m0] = pa0.y;
    As[0][a_kq0 * 4 + 2][a_m0] = pa0.z;
    As[0][a_kq0 * 4 + 3][a_m0] = pa0.w;
    As[0][a_kq1 * 4 + 0][a_m1] = pa1.x;
    As[0][a_kq1 * 4 + 1][a_m1] = pa1.y;
    As[0][a_kq1 * 4 + 2][a_m1] = pa1.z;
    As[0][a_kq1 * 4 + 3][a_m1] = pa1.w;
    *(float4*)&Bs[0][b_k0][b_n40 * 4] = pb0;
    *(float4*)&Bs[0][b_k1][b_n41 * 4] = pb1;
    __syncthreads();

#pragma unroll
    for (int kc = 0; kc < 8; kc++) {
        int cur = kc & 1;
        // prefetch next chunk (LDGs in flight during compute)
        if (kc < 7) {
            int kn = (kc + 1) * BK;
            pa0 = ok0 ? *(const float4*)&A[(size_t)r0 * 128 + kn + a_kq0 * 4] : z4;
            pa1 = ok1 ? *(const float4*)&A[(size_t)r1 * 128 + kn + a_kq1 * 4] : z4;
            pb0 = *(const float4*)&B[(size_t)(kn + b_k0) * 128 + b_n40 * 4];
            pb1 = *(const float4*)&B[(size_t)(kn + b_k1) * 128 + b_n41 * 4];
        }

#pragma unroll
        for (int kk = 0; kk < BK; kk++) {
            float4 a0 = *(const float4*)&As[cur][kk][ty * 8];
            float4 a1 = *(const float4*)&As[cur][kk][ty * 8 + 4];
            const unsigned long long* bp = (const unsigned long long*)&Bs[cur][kk][tx * 8];
            unsigned long long b0 = bp[0], b1 = bp[1], b2 = bp[2], b3 = bp[3];
            float av[8] = {a0.x, a0.y, a0.z, a0.w, a1.x, a1.y, a1.z, a1.w};
#pragma unroll
            for (int i = 0; i < 8; i++) {
                unsigned long long ai = dup2(av[i]);
                fma2(acc[i][0], ai, b0);
                fma2(acc[i][1], ai, b1);
                fma2(acc[i][2], ai, b2);
                fma2(acc[i][3], ai, b3);
            }
        }

        if (kc < 7) {
            int nxt = cur ^ 1;
            As[nxt][a_kq0 * 4 + 0][a_m0] = pa0.x;
            As[nxt][a_kq0 * 4 + 1][a_m0] = pa0.y;
            As[nxt][a_kq0 * 4 + 2][a_m0] = pa0.z;
            As[nxt][a_kq0 * 4 + 3][a_m0] = pa0.w;
            As[nxt][a_kq1 * 4 + 0][a_m1] = pa1.x;
            As[nxt][a_kq1 * 4 + 1][a_m1] = pa1.y;
            As[nxt][a_kq1 * 4 + 2][a_m1] = pa1.z;
            As[nxt][a_kq1 * 4 + 3][a_m1] = pa1.w;
            *(float4*)&Bs[nxt][b_k0][b_n40 * 4] = pb0;
            *(float4*)&Bs[nxt][b_k1][b_n41 * 4] = pb1;
            __syncthreads();
        }
    }

    float bv[8] = {0.f, 0.f, 0.f, 0.f, 0.f, 0.f, 0.f, 0.f};
    if (bias) {
#pragma unroll
        for (int j = 0; j < 8; j++) bv[j] = bias[tx * 8 + j];
    }
#pragma unroll
    for (int i = 0; i < 8; i++) {
        int row = blockM + ty * 8 + i;
        if (row >= M) continue;
        float2 p0 = unpk2(acc[i][0]), p1 = unpk2(acc[i][1]);
        float2 p2 = unpk2(acc[i][2]), p3 = unpk2(acc[i][3]);
        float c[8] = {p0.x + bv[0], p0.y + bv[1], p1.x + bv[2], p1.y + bv[3],
                      p2.x + bv[4], p2.y + bv[5], p3.x + bv[6], p3.y + bv[7]};
        if (half_out) {
            __half2 h[4];
#pragma unroll
            for (int j = 0; j < 4; j++) h[j] = __floats2half2_rn(c[2 * j], c[2 * j + 1]);
            *(uint4*)&g_xh[(size_t)row * 128 + tx * 8] = *(uint4*)h;
        } else {
            *(float4*)&C[(size_t)row * 128 + tx * 8] = make_float4(c[0], c[1], c[2], c[3]);
            *(float4*)&C[(size_t)row * 128 + tx * 8 + 4] =
                make_float4(c[4], c[5], c[6], c[7]);
        }
    }
}

// ---------------- CSR aggregation (fp16 gather) + fused BN stats ----------------
__device__ __forceinline__ float4 ldx_h(int u, int lane) {
    uint2 raw = ((const uint2*)(g_xh + (size_t)u * 128))[lane];
    __half2 h0 = *(__half2*)&raw.x;
    __half2 h1 = *(__half2*)&raw.y;
    float2 f0 = __half22float2(h0);
    float2 f1 = __half22float2(h1);
    return make_float4(f0.x, f0.y, f1.x, f1.y);
}

__global__ void k_agg(const float* __restrict__ bias, int layer) {
    __shared__ float s_sum[8][HID];
    __shared__ float s_ss[8][HID];
    int lane = threadIdx.x & 31;
    int wblk = threadIdx.x >> 5;
    int w = (blockIdx.x * blockDim.x + threadIdx.x) >> 5;
    int nw = (gridDim.x * blockDim.x) >> 5;
    float4 bb = ((const float4*)bias)[lane];
    float4 ls = make_float4(0.f, 0.f, 0.f, 0.f);
    float4 lss = make_float4(0.f, 0.f, 0.f, 0.f);

    for (int v = w; v < N_NODES; v += nw) {
        float dv = g_dinv[v];
        float4 xv = ldx_h(v, lane);
        float4 acc = make_float4(xv.x * dv, xv.y * dv, xv.z * dv, xv.w * dv);
        int s = g_rowptr[v], e = g_rowptr[v + 1];
        int p = s;
        for (; p + 4 <= e; p += 4) {
            int u0 = g_col[p], u1 = g_col[p + 1], u2 = g_col[p + 2], u3 = g_col[p + 3];
            float d0 = g_dinv[u0], d1 = g_dinv[u1], d2 = g_dinv[u2], d3 = g_dinv[u3];
            float4 x0 = ldx_h(u0, lane);
            float4 x1 = ldx_h(u1, lane);
            float4 x2 = ldx_h(u2, lane);
            float4 x3 = ldx_h(u3, lane);
            acc.x += x0.x * d0 + x1.x * d1 + x2.x * d2 + x3.x * d3;
            acc.y += x0.y * d0 + x1.y * d1 + x2.y * d2 + x3.y * d3;
            acc.z += x0.z * d0 + x1.z * d1 + x2.z * d2 + x3.z * d3;
            acc.w += x0.w * d0 + x1.w * d1 + x2.w * d2 + x3.w * d3;
        }
        for (; p < e; p++) {
            int u = g_col[p];
            float du = g_dinv[u];
            float4 xu = ldx_h(u, lane);
            acc.x += xu.x * du;
            acc.y += xu.y * du;
            acc.z += xu.z * du;
            acc.w += xu.w * du;
        }
        float4 o;
        o.x = acc.x * dv + bb.x;
        o.y = acc.y * dv + bb.y;
        o.z = acc.z * dv + bb.z;
        o.w = acc.w * dv + bb.w;
        ((float4*)(g_agg + (size_t)v * 128))[lane] = o;
        ls.x += o.x; ls.y += o.y; ls.z += o.z; ls.w += o.w;
        lss.x += o.x * o.x; lss.y += o.y * o.y; lss.z += o.z * o.z; lss.w += o.w * o.w;
    }

    ((float4*)&s_sum[wblk][lane * 4])[0] = ls;
    ((float4*)&s_ss[wblk][lane * 4])[0] = lss;
    __syncthreads();
    if (threadIdx.x < HID) {
        int f = threadIdx.x;
        float ts = 0.f, tss = 0.f;
#pragma unroll
        for (int k = 0; k < 8; k++) { ts += s_sum[k][f]; tss += s_ss[k][f]; }
        atomicAdd(&g_sum[layer * HID + f], ts);
        atomicAdd(&g_sumsq[layer * HID + f], tss);
    }
}

// ---------------- apply: hout = hin + relu(agg*scale + shift) ----------------
__global__ void k_apply(int hin_sel, int hout_sel, int layer,
                        const float* __restrict__ gamma, const float* __restrict__ beta) {
    __shared__ float s_scale[HID];
    __shared__ float s_shift[HID];
    if (threadIdx.x < HID) {
        int f = threadIdx.x;
        const float invn = 1.0f / (float)N_NODES;
        float mu = g_sum[layer * HID + f] * invn;
        float var = fmaxf(g_sumsq[layer * HID + f] * invn - mu * mu, 0.f);
        float sc = gamma[f] * rsqrtf(var + BN_EPS);
        s_scale[f] = sc;
        s_shift[f] = beta[f] - mu * sc;
    }
    __syncthreads();
    int i = blockIdx.x * blockDim.x + threadIdx.x;
    if (i >= N_NODES * 32) return;
    const float* hin = pick(hin_sel);
    float* hout = pick(hout_sel);
    int f4 = i & 31;
    float4 sc = ((const float4*)s_scale)[f4];
    float4 sh = ((const float4*)s_shift)[f4];
    float4 a = ((const float4*)g_agg)[i];
    float4 h = ((const float4*)hin)[i];
    float4 o;
    o.x = h.x + fmaxf(a.x * sc.x + sh.x, 0.f);
    o.y = h.y + fmaxf(a.y * sc.y + sh.y, 0.f);
    o.z = h.z + fmaxf(a.z * sc.z + sh.z, 0.f);
    o.w = h.w + fmaxf(a.w * sc.w + sh.w, 0.f);
    ((float4*)hout)[i] = o;
}

// ---------------- final classifier: warp per row, W in registers ----------------
__global__ void k_final(int h_sel, const float* __restrict__ W,
                        const float* __restrict__ b, float* __restrict__ out) {
    int lane = threadIdx.x & 31;
    int w0 = (blockIdx.x * blockDim.x + threadIdx.x) >> 5;
    int nw = (gridDim.x * blockDim.x) >> 5;
    const float* h = pick(h_sel);
    float wr[4][N_CLASSES];
#pragma unroll
    for (int j = 0; j < 4; j++)
#pragma unroll
        for (int c = 0; c < N_CLASSES; c++) wr[j][c] = W[(lane * 4 + j) * N_CLASSES + c];
    for (int row = w0; row < N_NODES; row += nw) {
        float4 hv = ((const float4*)(h + (size_t)row * 128))[lane];
        float p[N_CLASSES];
#pragma unroll
        for (int c = 0; c < N_CLASSES; c++)
            p[c] = hv.x * wr[0][c] + hv.y * wr[1][c] + hv.z * wr[2][c] + hv.w * wr[3][c];
#pragma unroll
        for (int c = 0; c < N_CLASSES; c++)
#pragma unroll
            for (int off = 16; off; off >>= 1)
                p[c] += __shfl_xor_sync(0xffffffffu, p[c], off);
        if (lane == 0) {
#pragma unroll
            for (int c = 0; c < N_CLASSES; c++) out[(size_t)row * N_CLASSES + c] = p[c] + b[c];
        }
    }
}

// ---------------- launch ----------------
extern "C" void kernel_launch(void* const* d_in, const int* in_sizes, int n_in,
                              void* d_out, int out_size) {
    const float* h_in = (const float*)d_in[0];
    const int* ei = (const int*)d_in[1];   // int32 or int64 (auto-detected)
    const float* W_emb = (const float*)d_in[3];
    const float* b_emb = (const float*)d_in[4];
    const float* Ws = (const float*)d_in[5];
    const float* bs = (const float*)d_in[6];
    const float* gammas = (const float*)d_in[7];
    const float* betas = (const float*)d_in[8];
    const float* W_mlp = (const float*)d_in[9];
    const float* b_mlp = (const float*)d_in[10];
    float* out = (float*)d_out;

    k_init<<<196, 256>>>(ei);
    k_count<<<E_EDGES / 256, 256>>>(ei);
    k_blksum<<<SCAN_BLOCKS, 256>>>();
    k_scanblk<<<1, 256>>>();
    k_rowptr<<<SCAN_BLOCKS, 256>>>();
    k_fill<<<E_EDGES / 256, 256>>>(ei);

    const int gemm_grid = (N_NODES + 127) / 128;  // 391
    // embedding: bufA = h_in @ W_emb + b_emb  (fp32 out)
    k_gemm<<<gemm_grid, 256>>>(h_in, 0, W_emb, b_emb, 1, 0, N_NODES);

    int hc = 1, ho = 2;  // selectors: 1=bufA, 2=bufB
    for (int i = 0; i < L_LAYERS; i++) {
        k_gemm<<<gemm_grid, 256>>>(nullptr, hc, Ws + (size_t)i * HID * HID, nullptr, 0, 1,
                                   N_NODES);
        k_agg<<<2048, 256>>>(bs + i * HID, i);
        k_apply<<<(N_NODES * 32 + 255) / 256, 256>>>(hc, ho, i, gammas + i * HID,
                                                     betas + i * HID);
        int t = hc; hc = ho; ho = t;
    }
    k_final<<<6250, 256>>>(hc, W_mlp, b_mlp, out);
}